// round 5
// baseline (speedup 1.0000x reference)
#include <cuda_runtime.h>
#include <cuda_bf16.h>
#include <cstdint>

#define NN   1024
#define NN2  (NN * NN)
#define BD   64
#define NB   128
#define ROWB 80          // 64B k-data per row + 16B pad -> conflict-free ldmatrix

// ============================================================================
// Device global scratch (allocation-free rule)
// ============================================================================
__device__ __align__(16) __nv_bfloat16 g_Ss_hi[NN2], g_Ss_lo[NN2];   // S row-major
__device__ __align__(16) __nv_bfloat16 g_St_hi[NN2], g_St_lo[NN2];   // S^T row-major
__device__ __align__(16) __nv_bfloat16 g_W1h[NN2], g_W1l[NN2], g_W3h[NN2], g_W3l[NN2];
__device__ __align__(16) __nv_bfloat16 g_W5h[NN2], g_W5l[NN2], g_W7h[NN2], g_W7l[NN2];
__device__ __align__(16) __nv_bfloat16 g_Qh[NN2],  g_Ql[NN2],  g_Qth[NN2], g_Qtl[NN2];
__device__ __align__(16) __nv_bfloat16 g_C0h[NN2], g_C0l[NN2], g_C1h[NN2], g_C1l[NN2];
__device__ __align__(16) __nv_bfloat16 g_C2h[NN2], g_C2l[NN2], g_C3h[NN2], g_C3l[NN2];
__device__ __align__(16) __nv_bfloat16 g_B0h[NN2], g_B0l[NN2], g_B1h[NN2], g_B1l[NN2];
__device__ __align__(16) __nv_bfloat16 g_Q4th[NN2], g_Q4tl[NN2];
__device__ __align__(16) __nv_bfloat16 g_Afh[NN2], g_Afl[NN2];
__device__ __align__(16) __nv_bfloat16 g_Xt_hi[(size_t)NB * BD * NN];
__device__ __align__(16) __nv_bfloat16 g_Xt_lo[(size_t)NB * BD * NN];

// ============================================================================
// PTX helpers (baseline sm_80-class, legal under compute_103)
// ============================================================================
__device__ __forceinline__ uint32_t smem_to_u32(const void* p) {
    uint32_t a;
    asm("{ .reg .u64 t; cvta.to.shared.u64 t, %1; cvt.u32.u64 %0, t; }"
        : "=r"(a) : "l"(p));
    return a;
}
__device__ __forceinline__ void cp16(uint32_t s, const void* g) {
    asm volatile("cp.async.cg.shared.global [%0], [%1], 16;" :: "r"(s), "l"(g));
}
#define CP_COMMIT() asm volatile("cp.async.commit_group;" ::: "memory")
#define CP_WAIT(n)  asm volatile("cp.async.wait_group %0;" :: "n"(n) : "memory")

__device__ __forceinline__ void ldsm4(uint32_t& r0, uint32_t& r1,
                                      uint32_t& r2, uint32_t& r3, uint32_t a) {
    asm volatile("ldmatrix.sync.aligned.m8n8.x4.shared.b16 {%0,%1,%2,%3}, [%4];"
                 : "=r"(r0), "=r"(r1), "=r"(r2), "=r"(r3) : "r"(a));
}
__device__ __forceinline__ void mma16816(float* c, const uint32_t* a,
                                         uint32_t b0, uint32_t b1) {
    asm volatile(
        "mma.sync.aligned.m16n8k16.row.col.f32.bf16.bf16.f32 "
        "{%0,%1,%2,%3}, {%4,%5,%6,%7}, {%8,%9}, {%0,%1,%2,%3};"
        : "+f"(c[0]), "+f"(c[1]), "+f"(c[2]), "+f"(c[3])
        : "r"(a[0]), "r"(a[1]), "r"(a[2]), "r"(a[3]), "r"(b0), "r"(b1));
}

__device__ __forceinline__ void split_bf16(float v, __nv_bfloat16& h, __nv_bfloat16& l) {
    h = __float2bfloat16(v);
    l = __float2bfloat16(v - __bfloat162float(h));
}

// ============================================================================
// Converts
// ============================================================================
// St[n][k] = split(S[k][n])
__global__ __launch_bounds__(256) void convert_St(const float* __restrict__ S) {
    __shared__ float tile[64][65];
    int k0 = blockIdx.x * 64, n0 = blockIdx.y * 64;
    for (int idx = threadIdx.x; idx < 64 * 64; idx += 256) {
        int r = idx >> 6, c = idx & 63;
        tile[r][c] = S[(size_t)(k0 + r) * NN + n0 + c];
    }
    __syncthreads();
    for (int idx = threadIdx.x; idx < 64 * 64; idx += 256) {
        int r = idx >> 6, c = idx & 63;
        __nv_bfloat16 h, l; split_bf16(tile[c][r], h, l);
        size_t o = (size_t)(n0 + r) * NN + k0 + c;
        g_St_hi[o] = h; g_St_lo[o] = l;
    }
}
// elementwise splits: y=0 -> S -> Ss; y=1..4 -> W[2y-1] -> W(2y-1) split
__global__ __launch_bounds__(256)
void convert_elem(const float* __restrict__ S, const float* __restrict__ weight) {
    size_t i = (size_t)blockIdx.x * 256 + threadIdx.x;
    int y = blockIdx.y;
    const float* src;
    __nv_bfloat16 *dh, *dl;
    if (y == 0)      { src = S;                                dh = g_Ss_hi; dl = g_Ss_lo; }
    else if (y == 1) { src = weight + (size_t)1 * NN2;         dh = g_W1h;   dl = g_W1l; }
    else if (y == 2) { src = weight + (size_t)3 * NN2;         dh = g_W3h;   dl = g_W3l; }
    else if (y == 3) { src = weight + (size_t)5 * NN2;         dh = g_W5h;   dl = g_W5l; }
    else             { src = weight + (size_t)7 * NN2;         dh = g_W7h;   dl = g_W7l; }
    __nv_bfloat16 h, l; split_bf16(src[i], h, l);
    dh[i] = h; dl[i] = l;
}
// Xt[b][d][k] = split(X[b][k][d])
__global__ __launch_bounds__(256) void convert_X(const float* __restrict__ X) {
    __shared__ float tile[64][65];
    int k0 = blockIdx.x * 64, b = blockIdx.y;
    for (int idx = threadIdx.x; idx < 64 * 64; idx += 256) {
        int r = idx >> 6, c = idx & 63;
        tile[r][c] = X[((size_t)b * NN + k0 + r) * BD + c];
    }
    __syncthreads();
    for (int idx = threadIdx.x; idx < 64 * 64; idx += 256) {
        int r = idx >> 6, c = idx & 63;
        __nv_bfloat16 h, l; split_bf16(tile[c][r], h, l);
        size_t o = ((size_t)b * BD + r) * NN + k0 + c;
        g_Xt_hi[o] = h; g_Xt_lo[o] = l;
    }
}

// ============================================================================
// Unified GEMM: C[m][n] = Aarr @ Barr^T over Kext=3072 (split-precision 3-term)
//   tile 128x128, 256 threads (warps 2Mx4N, warp tile 64x32), 4-stage cp.async.
// Levels:
//   0: z0 Q=S*S, z1 Qt=St*St, z2..5 Cj = W(2j+1)*S + W(2j)          [6 jobs]
//   1: z0 B0=C1*Q+C0, z1 B1=C3*Q+C2, z2 Q4t=Qt*Qt                   [3 jobs]
//   2: z0 Af = B1*Q4 + B0                                           [1 job]
//   3: final out = Af * Xstack (N=8192, fp32 scatter epilogue)
// ============================================================================
#define STG_BYTES (256 * ROWB)   // 128 A rows + 128 B rows = 20480 B
#define NSTAGE    4
#define OP_SMEM   (NSTAGE * STG_BYTES)

__global__ __launch_bounds__(256)
void gemm_op(int level, const float* __restrict__ weight, float* __restrict__ outp) {
    extern __shared__ __align__(16) char smem[];
    const int tid  = threadIdx.x;
    const int lane = tid & 31, w = tid >> 5;
    const int wm   = (w >> 2) * 64;
    const int wn   = (w & 3) * 32;
    const int row0 = blockIdx.y * 128;
    const int col0 = blockIdx.x * 128;
    const uint32_t sbase = smem_to_u32(smem);

    // ---- job resolution ----
    const __nv_bfloat16 *Ah, *Al, *Bh, *Bl;
    const __nv_bfloat16 *adH = nullptr, *adL = nullptr;
    const float* adF = nullptr;
    __nv_bfloat16 *Oh = nullptr, *Ol = nullptr;
    const int z = blockIdx.z;
    if (level == 0) {
        if (z == 0)      { Ah = g_Ss_hi; Al = g_Ss_lo; Bh = g_St_hi; Bl = g_St_lo;
                           Oh = g_Qh;  Ol = g_Ql; }
        else if (z == 1) { Ah = g_St_hi; Al = g_St_lo; Bh = g_Ss_hi; Bl = g_Ss_lo;
                           Oh = g_Qth; Ol = g_Qtl; }
        else {
            int j = z - 2;
            if (j == 0)      { Ah = g_W1h; Al = g_W1l; Oh = g_C0h; Ol = g_C0l; }
            else if (j == 1) { Ah = g_W3h; Al = g_W3l; Oh = g_C1h; Ol = g_C1l; }
            else if (j == 2) { Ah = g_W5h; Al = g_W5l; Oh = g_C2h; Ol = g_C2l; }
            else             { Ah = g_W7h; Al = g_W7l; Oh = g_C3h; Ol = g_C3l; }
            Bh = g_St_hi; Bl = g_St_lo;
            adF = weight + (size_t)(2 * j) * NN2;
        }
    } else if (level == 1) {
        if (z == 0)      { Ah = g_C1h; Al = g_C1l; Bh = g_Qth; Bl = g_Qtl;
                           adH = g_C0h; adL = g_C0l; Oh = g_B0h; Ol = g_B0l; }
        else if (z == 1) { Ah = g_C3h; Al = g_C3l; Bh = g_Qth; Bl = g_Qtl;
                           adH = g_C2h; adL = g_C2l; Oh = g_B1h; Ol = g_B1l; }
        else             { Ah = g_Qth; Al = g_Qtl; Bh = g_Qh; Bl = g_Ql;
                           Oh = g_Q4th; Ol = g_Q4tl; }
    } else if (level == 2) {
        Ah = g_B1h; Al = g_B1l; Bh = g_Q4th; Bl = g_Q4tl;
        adH = g_B0h; adL = g_B0l; Oh = g_Afh; Ol = g_Afl;
    } else {
        Ah = g_Afh; Al = g_Afl; Bh = g_Xt_hi; Bl = g_Xt_lo;
    }

    // ---- pipeline ----
    auto loadStage = [&](int s, int slot) {
        const int kk  = s * 32;
        const int seg = kk >> 10;
        const int k   = kk & 1023;
        const __nv_bfloat16* Ap = (seg < 2) ? Ah : Al;
        const __nv_bfloat16* Bp = (seg == 1) ? Bl : Bh;
        const uint32_t base = sbase + slot * STG_BYTES;
        #pragma unroll
        for (int i = 0; i < 4; ++i) {
            int idx = tid + i * 256;           // 0..1023
            int r = idx >> 2, c = idx & 3;
            const __nv_bfloat16* src = (r < 128)
                ? Ap + (size_t)(row0 + r) * NN + k + c * 8
                : Bp + (size_t)(col0 + r - 128) * NN + k + c * 8;
            cp16(base + r * ROWB + c * 16, src);
        }
        CP_COMMIT();
    };

    float acc[4][4][4] = {};
    loadStage(0, 0); loadStage(1, 1); loadStage(2, 2);

    for (int s = 0; s < 96; ++s) {
        CP_WAIT(2);
        __syncthreads();
        const uint32_t sA = sbase + (s & 3) * STG_BYTES;
        const uint32_t sB = sA + 128 * ROWB;

        uint32_t a[4][4], b[2][4];
        // k16 = 0 fragments first (latency overlapped with cp.async issue below)
        #pragma unroll
        for (int mt = 0; mt < 4; ++mt)
            ldsm4(a[mt][0], a[mt][1], a[mt][2], a[mt][3],
                  sA + (uint32_t)(wm + mt * 16 + (lane & 15)) * ROWB
                     + (uint32_t)(lane >> 4) * 16);
        #pragma unroll
        for (int p = 0; p < 2; ++p)
            ldsm4(b[p][0], b[p][1], b[p][2], b[p][3],
                  sB + (uint32_t)(wn + p * 16 + ((lane >> 4) << 3) + (lane & 7)) * ROWB
                     + (uint32_t)((lane >> 3) & 1) * 16);

        if (s + 3 < 96) loadStage(s + 3, (s + 3) & 3);
        else            CP_COMMIT();

        #pragma unroll
        for (int mt = 0; mt < 4; ++mt)
            #pragma unroll
            for (int nt = 0; nt < 4; ++nt)
                mma16816(acc[mt][nt], a[mt],
                         b[nt >> 1][(nt & 1) * 2], b[nt >> 1][(nt & 1) * 2 + 1]);

        // k16 = 1
        #pragma unroll
        for (int mt = 0; mt < 4; ++mt)
            ldsm4(a[mt][0], a[mt][1], a[mt][2], a[mt][3],
                  sA + (uint32_t)(wm + mt * 16 + (lane & 15)) * ROWB
                     + (uint32_t)(2 + (lane >> 4)) * 16);
        #pragma unroll
        for (int p = 0; p < 2; ++p)
            ldsm4(b[p][0], b[p][1], b[p][2], b[p][3],
                  sB + (uint32_t)(wn + p * 16 + ((lane >> 4) << 3) + (lane & 7)) * ROWB
                     + (uint32_t)(2 + ((lane >> 3) & 1)) * 16);
        #pragma unroll
        for (int mt = 0; mt < 4; ++mt)
            #pragma unroll
            for (int nt = 0; nt < 4; ++nt)
                mma16816(acc[mt][nt], a[mt],
                         b[nt >> 1][(nt & 1) * 2], b[nt >> 1][(nt & 1) * 2 + 1]);
    }

    // ---- epilogue ----
    const int g  = lane >> 2;
    const int i2 = (lane & 3) * 2;
    if (level == 3) {
        #pragma unroll
        for (int mt = 0; mt < 4; ++mt)
            #pragma unroll
            for (int nt = 0; nt < 4; ++nt) {
                const int m0    = row0 + wm + mt * 16 + g;
                const int ncolg = col0 + wn + nt * 8 + i2;
                const int batch = ncolg >> 6;
                const int d     = ncolg & 63;
                float* o0 = outp + ((size_t)batch * NN + m0) * BD + d;
                float* o1 = outp + ((size_t)batch * NN + m0 + 8) * BD + d;
                *(float2*)o0 = make_float2(acc[mt][nt][0], acc[mt][nt][1]);
                *(float2*)o1 = make_float2(acc[mt][nt][2], acc[mt][nt][3]);
            }
        return;
    }
    #pragma unroll
    for (int mt = 0; mt < 4; ++mt)
        #pragma unroll
        for (int nt = 0; nt < 4; ++nt) {
            const int m0 = row0 + wm + mt * 16 + g;
            const int n  = col0 + wn + nt * 8 + i2;
            float add00 = 0.f, add01 = 0.f, add10 = 0.f, add11 = 0.f;
            if (adF) {
                float2 w0 = *(const float2*)(adF + (size_t)m0 * NN + n);
                float2 w1 = *(const float2*)(adF + (size_t)(m0 + 8) * NN + n);
                add00 = w0.x; add01 = w0.y; add10 = w1.x; add11 = w1.y;
            } else if (adH) {
                __nv_bfloat162 h0 = *(const __nv_bfloat162*)(adH + (size_t)m0 * NN + n);
                __nv_bfloat162 l0 = *(const __nv_bfloat162*)(adL + (size_t)m0 * NN + n);
                __nv_bfloat162 h1 = *(const __nv_bfloat162*)(adH + (size_t)(m0 + 8) * NN + n);
                __nv_bfloat162 l1 = *(const __nv_bfloat162*)(adL + (size_t)(m0 + 8) * NN + n);
                add00 = __bfloat162float(h0.x) + __bfloat162float(l0.x);
                add01 = __bfloat162float(h0.y) + __bfloat162float(l0.y);
                add10 = __bfloat162float(h1.x) + __bfloat162float(l1.x);
                add11 = __bfloat162float(h1.y) + __bfloat162float(l1.y);
            }
            float v00 = acc[mt][nt][0] + add00, v01 = acc[mt][nt][1] + add01;
            float v10 = acc[mt][nt][2] + add10, v11 = acc[mt][nt][3] + add11;
            __nv_bfloat16 h0, l0, h1, l1;
            __nv_bfloat162 ph, pl;
            split_bf16(v00, h0, l0); split_bf16(v01, h1, l1);
            ph.x = h0; ph.y = h1; pl.x = l0; pl.y = l1;
            *(__nv_bfloat162*)(Oh + (size_t)m0 * NN + n) = ph;
            *(__nv_bfloat162*)(Ol + (size_t)m0 * NN + n) = pl;
            split_bf16(v10, h0, l0); split_bf16(v11, h1, l1);
            ph.x = h0; ph.y = h1; pl.x = l0; pl.y = l1;
            *(__nv_bfloat162*)(Oh + (size_t)(m0 + 8) * NN + n) = ph;
            *(__nv_bfloat162*)(Ol + (size_t)(m0 + 8) * NN + n) = pl;
        }
}

// ============================================================================
// Host orchestration (log-depth operator tree):
//   Cj = W2j + W2j+1*S ; Bi = C2i + C2i+1*S^2 ; Af = B0 + B1*S^4 ; out = Af*X
// ============================================================================
extern "C" void kernel_launch(void* const* d_in, const int* in_sizes, int n_in,
                              void* d_out, int out_size) {
    const float* nodes  = (const float*)d_in[0];   // [128, 1024, 64]
    const float* weight = (const float*)d_in[1];   // [8, 1024, 1024]
    const float* S      = (const float*)d_in[2];   // [1024, 1024]
    float* out = (float*)d_out;                    // [128, 1024, 64]

    cudaFuncSetAttribute(gemm_op, cudaFuncAttributeMaxDynamicSharedMemorySize, OP_SMEM);

    convert_St  <<<dim3(16, 16), 256>>>(S);
    convert_elem<<<dim3(NN2 / 256, 5), 256>>>(S, weight);
    convert_X   <<<dim3(16, NB), 256>>>(nodes);

    gemm_op<<<dim3(8, 8, 6),  256, OP_SMEM>>>(0, weight, nullptr);  // Q, Qt, C0..C3
    gemm_op<<<dim3(8, 8, 3),  256, OP_SMEM>>>(1, weight, nullptr);  // B0, B1, Q4t
    gemm_op<<<dim3(8, 8, 1),  256, OP_SMEM>>>(2, weight, nullptr);  // Af
    gemm_op<<<dim3(64, 8, 1), 256, OP_SMEM>>>(3, weight, out);      // out = Af*X
}

// round 6
// speedup vs baseline: 1.3851x; 1.3851x over previous
#include <cuda_runtime.h>
#include <cuda_bf16.h>
#include <cstdint>

#define NN   1024
#define NN2  (NN * NN)
#define BD   64
#define NB   128
#define ROWB 144         // 128B k-data (BK=64) + 16B pad; conflict-free per ldsm phase

// ============================================================================
// Device global scratch (allocation-free rule)
// ============================================================================
__device__ __align__(16) __nv_bfloat16 g_St_hi[NN2], g_St_lo[NN2];
__device__ __align__(16) __nv_bfloat16 g_Ta_hi[NN2], g_Ta_lo[NN2];
__device__ __align__(16) __nv_bfloat16 g_Tb_hi[NN2], g_Tb_lo[NN2];
__device__ __align__(16) __nv_bfloat16 g_Xt_hi[(size_t)NB * BD * NN];
__device__ __align__(16) __nv_bfloat16 g_Xt_lo[(size_t)NB * BD * NN];
__device__ __align__(16) float g_part[4][NN2];

// ============================================================================
// PTX helpers (baseline sm_80-class, legal under compute_103)
// ============================================================================
__device__ __forceinline__ uint32_t smem_to_u32(const void* p) {
    uint32_t a;
    asm("{ .reg .u64 t; cvta.to.shared.u64 t, %1; cvt.u32.u64 %0, t; }"
        : "=r"(a) : "l"(p));
    return a;
}
__device__ __forceinline__ void cp16(uint32_t s, const void* g) {
    asm volatile("cp.async.cg.shared.global [%0], [%1], 16;" :: "r"(s), "l"(g));
}
#define CP_COMMIT() asm volatile("cp.async.commit_group;" ::: "memory")
#define CP_WAIT(n)  asm volatile("cp.async.wait_group %0;" :: "n"(n) : "memory")

__device__ __forceinline__ void ldsm4(uint32_t& r0, uint32_t& r1,
                                      uint32_t& r2, uint32_t& r3, uint32_t a) {
    asm volatile("ldmatrix.sync.aligned.m8n8.x4.shared.b16 {%0,%1,%2,%3}, [%4];"
                 : "=r"(r0), "=r"(r1), "=r"(r2), "=r"(r3) : "r"(a));
}
__device__ __forceinline__ void mma16816(float* c, const uint32_t* a,
                                         uint32_t b0, uint32_t b1) {
    asm volatile(
        "mma.sync.aligned.m16n8k16.row.col.f32.bf16.bf16.f32 "
        "{%0,%1,%2,%3}, {%4,%5,%6,%7}, {%8,%9}, {%0,%1,%2,%3};"
        : "+f"(c[0]), "+f"(c[1]), "+f"(c[2]), "+f"(c[3])
        : "r"(a[0]), "r"(a[1]), "r"(a[2]), "r"(a[3]), "r"(b0), "r"(b1));
}

__device__ __forceinline__ void split_bf16(float v, __nv_bfloat16& h, __nv_bfloat16& l) {
    h = __float2bfloat16(v);
    l = __float2bfloat16(v - __bfloat162float(h));
}

// ============================================================================
// Converts
// ============================================================================
// St[n][k] = split(S[k][n])
__global__ __launch_bounds__(256) void convert_St(const float* __restrict__ S) {
    __shared__ float tile[64][65];
    int k0 = blockIdx.x * 64, n0 = blockIdx.y * 64;
    for (int idx = threadIdx.x; idx < 64 * 64; idx += 256) {
        int r = idx >> 6, c = idx & 63;
        tile[r][c] = S[(size_t)(k0 + r) * NN + n0 + c];
    }
    __syncthreads();
    for (int idx = threadIdx.x; idx < 64 * 64; idx += 256) {
        int r = idx >> 6, c = idx & 63;
        __nv_bfloat16 h, l; split_bf16(tile[c][r], h, l);
        size_t o = (size_t)(n0 + r) * NN + k0 + c;
        g_St_hi[o] = h; g_St_lo[o] = l;
    }
}
// Xt[b][d][k] = split(X[b][k][d])
__global__ __launch_bounds__(256) void convert_X(const float* __restrict__ X) {
    __shared__ float tile[64][65];
    int k0 = blockIdx.x * 64, b = blockIdx.y;
    for (int idx = threadIdx.x; idx < 64 * 64; idx += 256) {
        int r = idx >> 6, c = idx & 63;
        tile[r][c] = X[((size_t)b * NN + k0 + r) * BD + c];
    }
    __syncthreads();
    for (int idx = threadIdx.x; idx < 64 * 64; idx += 256) {
        int r = idx >> 6, c = idx & 63;
        __nv_bfloat16 h, l; split_bf16(tile[c][r], h, l);
        size_t o = ((size_t)b * BD + r) * NN + k0 + c;
        g_Xt_hi[o] = h; g_Xt_lo[o] = l;
    }
}
// Ta = split(W7)
__global__ __launch_bounds__(256) void convert_init(const float* __restrict__ W7) {
    size_t i = (size_t)blockIdx.x * 256 + threadIdx.x;
    __nv_bfloat16 h, l; split_bf16(W7[i], h, l);
    g_Ta_hi[i] = h; g_Ta_lo[i] = l;
}

// ============================================================================
// Shared GEMM core pieces: tile 128x128, 256 thr (warps 2Mx4N, warp 64x32),
// BK=64, 3-stage cp.async ring.  Stage = 256 rows x 144B = 36864 B.
// ============================================================================
#define STG_BYTES (256 * ROWB)
#define OP_SMEM   (3 * STG_BYTES)

#define LOAD_STAGE(Ap, Bp, k, slot)                                           \
    do {                                                                      \
        const uint32_t _base = sbase + (slot) * STG_BYTES;                    \
        _Pragma("unroll")                                                     \
        for (int _i = 0; _i < 8; ++_i) {                                      \
            int _idx = tid + _i * 256;                                        \
            int _r = _idx >> 3, _c = _idx & 7;                                \
            const __nv_bfloat16* _src = (_r < 128)                            \
                ? (Ap) + (size_t)(row0 + _r) * NN + (k) + _c * 8              \
                : (Bp) + (size_t)(col0 + _r - 128) * NN + (k) + _c * 8;       \
            cp16(_base + _r * ROWB + _c * 16, _src);                          \
        }                                                                     \
        CP_COMMIT();                                                          \
    } while (0)

#define LDS_A(a, k16, sA)                                                     \
    _Pragma("unroll")                                                         \
    for (int _mt = 0; _mt < 4; ++_mt)                                         \
        ldsm4((a)[_mt][0], (a)[_mt][1], (a)[_mt][2], (a)[_mt][3],             \
              (sA) + (uint32_t)(wm + _mt * 16 + (lane & 15)) * ROWB           \
                   + (uint32_t)((k16) * 2 + (lane >> 4)) * 16)

#define LDS_B(b, k16, sB)                                                     \
    _Pragma("unroll")                                                         \
    for (int _p = 0; _p < 2; ++_p)                                            \
        ldsm4((b)[_p][0], (b)[_p][1], (b)[_p][2], (b)[_p][3],                 \
              (sB) + (uint32_t)(wn + _p * 16 + ((lane >> 4) << 3) + (lane & 7)) * ROWB \
                   + (uint32_t)((k16) * 2 + ((lane >> 3) & 1)) * 16)

#define MMA_ALL(acc, a, b)                                                    \
    _Pragma("unroll")                                                         \
    for (int _mt = 0; _mt < 4; ++_mt)                                         \
        _Pragma("unroll")                                                     \
        for (int _nt = 0; _nt < 4; ++_nt)                                     \
            mma16816((acc)[_mt][_nt], (a)[_mt],                               \
                     (b)[_nt >> 1][(_nt & 1) * 2], (b)[_nt >> 1][(_nt & 1) * 2 + 1])

// ============================================================================
// gemm_splitk: partial[z] = T(rows) @ S^T(cols) over K-chunk z (768 of 3072)
// grid (8, 8, 4) = 256 CTAs.
// ============================================================================
__global__ __launch_bounds__(256, 2)
void gemm_splitk(int inSel) {
    extern __shared__ __align__(16) char smem[];
    const int tid  = threadIdx.x;
    const int lane = tid & 31, w = tid >> 5;
    const int wm   = (w >> 2) * 64;
    const int wn   = (w & 3) * 32;
    const int row0 = blockIdx.y * 128;
    const int col0 = blockIdx.x * 128;
    const int kb   = blockIdx.z * 768;
    const uint32_t sbase = smem_to_u32(smem);

    const __nv_bfloat16* Ah = inSel ? g_Tb_hi : g_Ta_hi;
    const __nv_bfloat16* Al = inSel ? g_Tb_lo : g_Ta_lo;

    auto issue = [&](int s, int slot) {
        const int kk  = kb + s * 64;
        const int seg = kk >> 10;
        const int k   = kk & 1023;
        const __nv_bfloat16* Ap = (seg < 2) ? Ah : Al;
        const __nv_bfloat16* Bp = (seg == 1) ? g_St_lo : g_St_hi;
        LOAD_STAGE(Ap, Bp, k, slot);
    };

    float acc[4][4][4] = {};
    issue(0, 0); issue(1, 1);

    for (int s = 0; s < 12; ++s) {
        CP_WAIT(1);
        __syncthreads();
        const uint32_t sA = sbase + (s % 3) * STG_BYTES;
        const uint32_t sB = sA + 128 * ROWB;

        uint32_t a[4][4], b[2][4];
        LDS_A(a, 0, sA); LDS_B(b, 0, sB);
        if (s + 2 < 12) issue(s + 2, (s + 2) % 3); else CP_COMMIT();
        MMA_ALL(acc, a, b);
        #pragma unroll
        for (int k16 = 1; k16 < 4; ++k16) {
            LDS_A(a, k16, sA); LDS_B(b, k16, sB);
            MMA_ALL(acc, a, b);
        }
    }

    float* P = g_part[blockIdx.z];
    const int g  = lane >> 2;
    const int i2 = (lane & 3) * 2;
    #pragma unroll
    for (int mt = 0; mt < 4; ++mt)
        #pragma unroll
        for (int nt = 0; nt < 4; ++nt) {
            const int m0 = row0 + wm + mt * 16 + g;
            const int n  = col0 + wn + nt * 8 + i2;
            *(float2*)(P + (size_t)m0 * NN + n)       = make_float2(acc[mt][nt][0], acc[mt][nt][1]);
            *(float2*)(P + (size_t)(m0 + 8) * NN + n) = make_float2(acc[mt][nt][2], acc[mt][nt][3]);
        }
}

// ============================================================================
// reduce_split: T_next = split(sum(parts) + Wk)   (4 elements per thread)
// ============================================================================
__global__ __launch_bounds__(256)
void reduce_split(const float* __restrict__ Wk, int inSel) {
    __nv_bfloat16* Oh = inSel ? g_Ta_hi : g_Tb_hi;   // write opposite of input
    __nv_bfloat16* Ol = inSel ? g_Ta_lo : g_Tb_lo;
    size_t i = ((size_t)blockIdx.x * 256 + threadIdx.x) * 4;
    float4 p0 = *(const float4*)&g_part[0][i];
    float4 p1 = *(const float4*)&g_part[1][i];
    float4 p2 = *(const float4*)&g_part[2][i];
    float4 p3 = *(const float4*)&g_part[3][i];
    float4 wv = *(const float4*)&Wk[i];
    float v0 = p0.x + p1.x + p2.x + p3.x + wv.x;
    float v1 = p0.y + p1.y + p2.y + p3.y + wv.y;
    float v2 = p0.z + p1.z + p2.z + p3.z + wv.z;
    float v3 = p0.w + p1.w + p2.w + p3.w + wv.w;
    __nv_bfloat16 h0, l0, h1, l1, h2, l2, h3, l3;
    split_bf16(v0, h0, l0); split_bf16(v1, h1, l1);
    split_bf16(v2, h2, l2); split_bf16(v3, h3, l3);
    __nv_bfloat162 a, bq;
    a.x = h0; a.y = h1; bq.x = h2; bq.y = h3;
    *(__nv_bfloat162*)(Oh + i)     = a;
    *(__nv_bfloat162*)(Oh + i + 2) = bq;
    a.x = l0; a.y = l1; bq.x = l2; bq.y = l3;
    *(__nv_bfloat162*)(Ol + i)     = a;
    *(__nv_bfloat162*)(Ol + i + 2) = bq;
}

// ============================================================================
// gemm_final: out = A_final @ Xcat  (Xcat as [8192 x 1024] row-major = Xt)
// grid (64, 8) = 512 CTAs.  K = 3072 -> 48 stages.
// ============================================================================
__global__ __launch_bounds__(256, 2)
void gemm_final(float* __restrict__ outp) {
    extern __shared__ __align__(16) char smem[];
    const int tid  = threadIdx.x;
    const int lane = tid & 31, w = tid >> 5;
    const int wm   = (w >> 2) * 64;
    const int wn   = (w & 3) * 32;
    const int row0 = blockIdx.y * 128;
    const int col0 = blockIdx.x * 128;     // global column in [0, 8192)
    const uint32_t sbase = smem_to_u32(smem);

    auto issue = [&](int s, int slot) {
        const int kk  = s * 64;
        const int seg = kk >> 10;
        const int k   = kk & 1023;
        const __nv_bfloat16* Ap = (seg < 2) ? g_Tb_hi : g_Tb_lo;
        const __nv_bfloat16* Bp = (seg == 1) ? g_Xt_lo : g_Xt_hi;
        LOAD_STAGE(Ap, Bp, k, slot);
    };

    float acc[4][4][4] = {};
    issue(0, 0); issue(1, 1);

    for (int s = 0; s < 48; ++s) {
        CP_WAIT(1);
        __syncthreads();
        const uint32_t sA = sbase + (s % 3) * STG_BYTES;
        const uint32_t sB = sA + 128 * ROWB;

        uint32_t a[4][4], b[2][4];
        LDS_A(a, 0, sA); LDS_B(b, 0, sB);
        if (s + 2 < 48) issue(s + 2, (s + 2) % 3); else CP_COMMIT();
        MMA_ALL(acc, a, b);
        #pragma unroll
        for (int k16 = 1; k16 < 4; ++k16) {
            LDS_A(a, k16, sA); LDS_B(b, k16, sB);
            MMA_ALL(acc, a, b);
        }
    }

    const int g  = lane >> 2;
    const int i2 = (lane & 3) * 2;
    #pragma unroll
    for (int mt = 0; mt < 4; ++mt)
        #pragma unroll
        for (int nt = 0; nt < 4; ++nt) {
            const int m0    = row0 + wm + mt * 16 + g;
            const int ncolg = col0 + wn + nt * 8 + i2;
            const int batch = ncolg >> 6;
            const int d     = ncolg & 63;
            float* o0 = outp + ((size_t)batch * NN + m0) * BD + d;
            float* o1 = outp + ((size_t)batch * NN + m0 + 8) * BD + d;
            *(float2*)o0 = make_float2(acc[mt][nt][0], acc[mt][nt][1]);
            *(float2*)o1 = make_float2(acc[mt][nt][2], acc[mt][nt][3]);
        }
}

// ============================================================================
// Host orchestration:
//   T = W7; for k = 6..0: T = T @ S + Wk  (split-K x4 + fused reduce);
//   out[b] = T @ X[b]
// ============================================================================
extern "C" void kernel_launch(void* const* d_in, const int* in_sizes, int n_in,
                              void* d_out, int out_size) {
    const float* nodes  = (const float*)d_in[0];   // [128, 1024, 64]
    const float* weight = (const float*)d_in[1];   // [8, 1024, 1024]
    const float* S      = (const float*)d_in[2];   // [1024, 1024]
    float* out = (float*)d_out;                    // [128, 1024, 64]

    cudaFuncSetAttribute(gemm_splitk, cudaFuncAttributeMaxDynamicSharedMemorySize, OP_SMEM);
    cudaFuncSetAttribute(gemm_final,  cudaFuncAttributeMaxDynamicSharedMemorySize, OP_SMEM);

    convert_St  <<<dim3(16, 16), 256>>>(S);
    convert_X   <<<dim3(16, NB), 256>>>(nodes);
    convert_init<<<NN2 / 256, 256>>>(weight + (size_t)7 * NN2);

    for (int step = 0; step < 7; ++step) {
        int inSel = step & 1;  // 0: read Ta (write Tb), 1: read Tb (write Ta)
        gemm_splitk <<<dim3(8, 8, 4), 256, OP_SMEM>>>(inSel);
        reduce_split<<<NN2 / 1024, 256>>>(weight + (size_t)(6 - step) * NN2, inSel);
    }
    // 7 steps: last step has inSel=0 -> final operator lands in Tb
    gemm_final<<<dim3(64, 8), 256, OP_SMEM>>>(out);
}